// round 12
// baseline (speedup 1.0000x reference)
#include <cuda_runtime.h>
#include <cuda_fp16.h>
#include <cstdint>
#include <math.h>

#define BSZ 2
#define HH 64
#define WW 80
#define NQ (HH*WW)          // 5120
#define EE 576
#define HEADS 18
#define HD 32
#define NPTS 12
#define NFR 3
#define DDEP 5
#define NV (NQ*DDEP)        // 25600
#define NOFF (HEADS*NPTS*3) // 648
#define NATT (HEADS*NPTS)   // 216
#define NOA  (NOFF+NATT)    // 864

// ---------------- scratch (device globals; no allocation allowed) ----------
__device__ float g_oa  [(size_t)BSZ*NQ*NOA];
__device__ float g_boa [NOA];

__device__ __align__(128) __half g_vf  [(size_t)BSZ*NV*EE];   // projected v, fp16
__device__ __align__(128) __half g_vh  [(size_t)BSZ*NV*EE];   // value hi
__device__ __align__(128) __half g_qh  [(size_t)BSZ*NQ*EE];   // q hi
__device__ __align__(128) __half g_sph [(size_t)BSZ*NQ*EE];   // samp (fp16)
__device__ __align__(128) __half g_wvh [(size_t)EE*EE];       // W_v hi
__device__ __align__(128) __half g_woa [(size_t)EE*NOA];      // [W_off|W_attn] hi
__device__ __align__(128) __half g_wuh [(size_t)EE*EE];       // W_out hi

// ================= helpers =================================================
__device__ __forceinline__ uint32_t smem_u32(const void* p) {
    uint32_t a;
    asm("{ .reg .u64 t; cvta.to.shared.u64 t, %1; cvt.u32.u64 %0, t; }" : "=r"(a) : "l"(p));
    return a;
}
__device__ __forceinline__ void ldsm_x4(uint32_t* r, uint32_t addr) {
    asm volatile("ldmatrix.sync.aligned.m8n8.x4.shared.b16 {%0,%1,%2,%3}, [%4];"
                 : "=r"(r[0]), "=r"(r[1]), "=r"(r[2]), "=r"(r[3]) : "r"(addr));
}
__device__ __forceinline__ void ldsm_x4_t(uint32_t* r, uint32_t addr) {
    asm volatile("ldmatrix.sync.aligned.m8n8.x4.trans.shared.b16 {%0,%1,%2,%3}, [%4];"
                 : "=r"(r[0]), "=r"(r[1]), "=r"(r[2]), "=r"(r[3]) : "r"(addr));
}
__device__ __forceinline__ void mma_f16(float* c, const uint32_t* a, const uint32_t* b) {
    asm volatile(
        "mma.sync.aligned.m16n8k16.row.col.f32.f16.f16.f32 "
        "{%0,%1,%2,%3}, {%4,%5,%6,%7}, {%8,%9}, {%0,%1,%2,%3};"
        : "+f"(c[0]), "+f"(c[1]), "+f"(c[2]), "+f"(c[3])
        : "r"(a[0]), "r"(a[1]), "r"(a[2]), "r"(a[3]), "r"(b[0]), "r"(b[1]));
}
__device__ __forceinline__ void cp16(uint32_t dst, const void* src) {
    asm volatile("cp.async.ca.shared.global [%0], [%1], 16;" :: "r"(dst), "l"(src));
}
__device__ __forceinline__ void cp16p(uint32_t dst, const void* src, int srcsize) {
    asm volatile("cp.async.ca.shared.global [%0], [%1], 16, %2;" :: "r"(dst), "l"(src), "r"(srcsize));
}
#define CP_COMMIT() asm volatile("cp.async.commit_group;" ::: "memory")
#define CP_WAIT1()  asm volatile("cp.async.wait_group 1;" ::: "memory")

__device__ __forceinline__ uint2 hi4(float4 v) {
    __half2 a = __floats2half2_rn(v.x, v.y);
    __half2 b = __floats2half2_rn(v.z, v.w);
    uint2 r;
    r.x = reinterpret_cast<uint32_t&>(a);
    r.y = reinterpret_cast<uint32_t&>(b);
    return r;
}

// ================= fused weight conversion =================================
#define NB_WV   324
#define NB_WU   324
#define NB_WO   1458
#define NB_WA   486
#define NB_BIAS 4
__global__ void convert_weights(const float4* __restrict__ W_v, const float4* __restrict__ W_out,
                                const float* __restrict__ W_off, const float* __restrict__ W_attn,
                                const float* __restrict__ b_off, const float* __restrict__ b_attn,
                                uint2* __restrict__ wvh, uint2* __restrict__ wuh,
                                __half* __restrict__ woa, float* __restrict__ boa) {
    int blk = blockIdx.x;
    if (blk < NB_WV) {
        int i = blk * 256 + threadIdx.x;
        if (i < (EE * EE) / 4) wvh[i] = hi4(W_v[i]);
    } else if (blk < NB_WV + NB_WU) {
        int i = (blk - NB_WV) * 256 + threadIdx.x;
        if (i < (EE * EE) / 4) wuh[i] = hi4(W_out[i]);
    } else if (blk < NB_WV + NB_WU + NB_WO) {
        int i = (blk - NB_WV - NB_WU) * 256 + threadIdx.x;
        if (i < EE * NOFF) {
            int k = i / NOFF, n = i % NOFF;
            woa[(size_t)k * NOA + n] = __float2half_rn(W_off[i]);
        }
    } else if (blk < NB_WV + NB_WU + NB_WO + NB_WA) {
        int i = (blk - NB_WV - NB_WU - NB_WO) * 256 + threadIdx.x;
        if (i < EE * NATT) {
            int k = i / NATT, n = i % NATT;
            woa[(size_t)k * NOA + NOFF + n] = __float2half_rn(W_attn[i]);
        }
    } else {
        int i = (blk - NB_WV - NB_WU - NB_WO - NB_WA) * 256 + threadIdx.x;
        if (i < NOA) boa[i] = (i < NOFF) ? b_off[i] : b_attn[i - NOFF];
    }
}

__global__ void split1_kernel(const float4* __restrict__ in, uint2* __restrict__ hi, int n4) {
    int i = blockIdx.x * blockDim.x + threadIdx.x;
    if (i < n4) hi[i] = hi4(in[i]);
}
__global__ void split_add1_kernel(const float4* __restrict__ a, const float4* __restrict__ b,
                                  uint2* __restrict__ hi, int n4) {
    int i = blockIdx.x * blockDim.x + threadIdx.x;
    if (i < n4) {
        float4 x = a[i], y = b[i];
        hi[i] = hi4(make_float4(x.x + y.x, x.y + y.y, x.z + y.z, x.w + y.w));
    }
}

// ================= fp16 HMMA GEMM, fat warp tiles ==========================
// C[M,N] = A @ B + bias.  Block 256x96x32, 8 warps (4m x 2n), warp tile 64x48.
// Compact 1-product stages, 3-deep cp.async pipeline.
#define BM 256
#define BN 96
#define BK 32
#define STAGES 3
#define SA 80
#define SB 208
#define A_BYTES (256*SA)          // 20480
#define B_BYTES (32*SB)           // 6656
#define OFF_BH A_BYTES
#define STAGE_SZ (A_BYTES + B_BYTES)       // 27136
#define SMEM_TOT (STAGES*STAGE_SZ)         // 81408

template<int OUTF16>
__global__ __launch_bounds__(256, 1)
void gemm_f16(const __half* __restrict__ Ah, const __half* __restrict__ Bh,
              const float* __restrict__ bias, void* __restrict__ Cv,
              int M, int N, int K) {
    extern __shared__ char smem[];
    uint32_t sbase = smem_u32(smem);
    const int tid = threadIdx.x;
    const int lane = tid & 31, wid = tid >> 5;
    const int warp_m = wid & 3, warp_n = wid >> 2;
    const int bm = blockIdx.y * BM;
    const int bn = blockIdx.x * BN;
    const int nchunk = K / BK;

    auto load_chunk = [&](int c, int s) {
        const int k0 = c * BK;
        char* sb = smem + s * STAGE_SZ;
        // A: 256 rows x 64B = 1024 x 16B -> 4 per thread
#pragma unroll
        for (int t = 0; t < 4; t++) {
            int idx = tid + t * 256, r = idx >> 2, c4 = idx & 3;
            uint32_t dst = smem_u32(sb + r * SA + c4 * 16);
            cp16(dst, &Ah[(size_t)(bm + r) * K + k0 + c4 * 8]);
        }
        // B: 32 rows x 192B = 384 x 16B
#pragma unroll
        for (int t = 0; t < 2; t++) {
            int idx = tid + t * 256;
            if (idx < 384) {
                int r = idx / 12, g = idx % 12;
                int col = bn + g * 8;
                int sz = (col < N) ? 16 : 0;
                uint32_t dst = smem_u32(sb + OFF_BH + r * SB + g * 16);
                cp16p(dst, &Bh[(size_t)(k0 + r) * N + col], sz);
            }
        }
    };

    float acc[4][6][4];
#pragma unroll
    for (int mi = 0; mi < 4; mi++)
#pragma unroll
        for (int ni = 0; ni < 6; ni++)
#pragma unroll
            for (int j = 0; j < 4; j++) acc[mi][ni][j] = 0.f;

    load_chunk(0, 0); CP_COMMIT();
    load_chunk(1, 1); CP_COMMIT();

    for (int c = 0; c < nchunk; c++) {
        CP_WAIT1();
        __syncthreads();
        if (c + 2 < nchunk) load_chunk(c + 2, (c + 2) % STAGES);
        CP_COMMIT();

        uint32_t sbuf = sbase + (c % STAGES) * STAGE_SZ;
#pragma unroll
        for (int ks = 0; ks < 2; ks++) {
            uint32_t a_hi[4][4], b_hi[6][2];
#pragma unroll
            for (int mi = 0; mi < 4; mi++) {
                uint32_t ad = sbuf
                    + (warp_m * 64 + mi * 16 + (lane & 15)) * SA
                    + ks * 32 + (lane >> 4) * 16;
                ldsm_x4(a_hi[mi], ad);
            }
#pragma unroll
            for (int nt = 0; nt < 3; nt++) {
                uint32_t bd = sbuf + OFF_BH
                    + (ks * 16 + (lane & 15)) * SB
                    + (warp_n * 48 + nt * 16) * 2 + (lane >> 4) * 16;
                uint32_t r[4];
                ldsm_x4_t(r, bd);
                b_hi[nt * 2][0] = r[0]; b_hi[nt * 2][1] = r[1];
                b_hi[nt * 2 + 1][0] = r[2]; b_hi[nt * 2 + 1][1] = r[3];
            }
#pragma unroll
            for (int mi = 0; mi < 4; mi++)
#pragma unroll
                for (int ni = 0; ni < 6; ni++)
                    mma_f16(acc[mi][ni], a_hi[mi], b_hi[ni]);
        }
    }

    __syncthreads();

    // ---- epilogue ----
    const int row_base = bm + warp_m * 64 + (lane >> 2);
    const int col_base = bn + warp_n * 48 + (lane & 3) * 2;
#pragma unroll
    for (int mi = 0; mi < 4; mi++)
#pragma unroll
        for (int r2 = 0; r2 < 2; r2++) {
            int row = row_base + mi * 16 + r2 * 8;
#pragma unroll
            for (int ni = 0; ni < 6; ni++) {
                int col = col_base + ni * 8;
                if (col < N) {
                    float ox = acc[mi][ni][r2 * 2 + 0] + bias[col];
                    float oy = acc[mi][ni][r2 * 2 + 1] + bias[col + 1];
                    if (OUTF16) {
                        __half2 pk = __floats2half2_rn(ox, oy);
                        *reinterpret_cast<__half2*>(
                            &((__half*)Cv)[(size_t)row * N + col]) = pk;
                    } else {
                        float2 o; o.x = ox; o.y = oy;
                        *reinterpret_cast<float2*>(&((float*)Cv)[(size_t)row * N + col]) = o;
                    }
                }
            }
        }
}

// ================= deformable 3D trilinear sampling (fp16 v) ===============
// Branch-free corners: clamped indices + validity folded into the weight, so
// all 8 corner loads per point are unconditional and can be batched.
__global__ __launch_bounds__(256)
void deform_sample(const __half* __restrict__ v, const float* __restrict__ oa,
                   __half* __restrict__ oh) {
    int wg = (blockIdx.x * blockDim.x + threadIdx.x) >> 5;
    int lane = threadIdx.x & 31;
    const int total = BSZ * HEADS * NQ;
    if (wg >= total) return;

    int q    = wg % NQ;
    int head = (wg / NQ) % HEADS;
    int b    = wg / (NQ * HEADS);
    size_t row = (size_t)b * NQ + q;

    int qx = q % WW;
    int qy = q / WW;
    float refx = ((float)qx + 0.5f) / (float)WW;
    float refy = ((float)qy + 0.5f) / (float)HH;

    const float* lgp = oa + row * NOA + NOFF + head * NPTS;
    float wt[NPTS];
    float mx = -1e30f;
#pragma unroll
    for (int p = 0; p < NPTS; p++) mx = fmaxf(mx, lgp[p]);
    float s = 0.f;
#pragma unroll
    for (int p = 0; p < NPTS; p++) { wt[p] = expf(lgp[p] - mx); s += wt[p]; }
    float invs = 1.f / s;

    const float* offp = oa + row * NOA + head * NPTS * 3;
    const __half* vbh = v + (size_t)b * NV * EE + head * HD + lane;

    float acc = 0.f;
#pragma unroll
    for (int p = 0; p < NPTS; p++) {
        float ox = offp[p * 3 + 0];
        float oy = offp[p * 3 + 1];
        float oz = offp[p * 3 + 2];
        float x = (refx + ox / (float)WW) * (float)WW - 0.5f;
        float y = (refy + oy / (float)HH) * (float)HH - 0.5f;
        float z = (oz / (float)NFR) * (float)DDEP - 0.5f;
        float x0f = floorf(x), y0f = floorf(y), z0f = floorf(z);
        float fx = x - x0f, fy = y - y0f, fz = z - z0f;
        int ix0 = (int)x0f, iy0 = (int)y0f, iz0 = (int)z0f;
        float ap = wt[p] * invs;

        // per-axis weights (validity folded in) + clamped coords
        float wxv[2], wyv[2], wzv[2];
        int xc[2], yc[2], zc[2];
#pragma unroll
        for (int d = 0; d < 2; d++) {
            int xi = ix0 + d, yi = iy0 + d, zi = iz0 + d;
            wxv[d] = (d ? fx : 1.f - fx) * (((unsigned)xi < WW)   ? 1.f : 0.f);
            wyv[d] = (d ? fy : 1.f - fy) * (((unsigned)yi < HH)   ? 1.f : 0.f);
            wzv[d] = (d ? fz : 1.f - fz) * (((unsigned)zi < DDEP) ? 1.f : 0.f);
            xc[d] = min(max(xi, 0), WW - 1);
            yc[d] = min(max(yi, 0), HH - 1);
            zc[d] = min(max(zi, 0), DDEP - 1);
        }
        float w8[8];
        float v8[8];
#pragma unroll
        for (int cor = 0; cor < 8; cor++) {
            int dz = cor >> 2, dy = (cor >> 1) & 1, dx = cor & 1;
            int idx = (zc[dz] * HH + yc[dy]) * WW + xc[dx];
            w8[cor] = wzv[dz] * wyv[dy] * wxv[dx];
            v8[cor] = __half2float(__ldg(&vbh[(size_t)idx * EE]));
        }
#pragma unroll
        for (int cor = 0; cor < 8; cor++)
            acc += ap * w8[cor] * v8[cor];
    }
    oh[row * EE + head * HD + lane] = __float2half_rn(acc);
}

// ================= launch ==================================================
extern "C" void kernel_launch(void* const* d_in, const int* in_sizes, int n_in,
                              void* d_out, int out_size) {
    const float* query  = (const float*)d_in[0];
    const float* value  = (const float*)d_in[1];
    const float* qpos   = (const float*)d_in[2];
    const float* W_off  = (const float*)d_in[3];
    const float* b_off  = (const float*)d_in[4];
    const float* W_attn = (const float*)d_in[5];
    const float* b_attn = (const float*)d_in[6];
    const float* W_v    = (const float*)d_in[7];
    const float* b_v    = (const float*)d_in[8];
    const float* W_out  = (const float*)d_in[9];
    const float* b_out  = (const float*)d_in[10];
    float* out = (float*)d_out;

    float *oa_s, *boa_s;
    __half *vf, *vh, *qh, *sph, *wvh, *woa, *wuh;
    cudaGetSymbolAddress((void**)&oa_s,  g_oa);
    cudaGetSymbolAddress((void**)&boa_s, g_boa);
    cudaGetSymbolAddress((void**)&vf,  g_vf);
    cudaGetSymbolAddress((void**)&vh,  g_vh);
    cudaGetSymbolAddress((void**)&qh,  g_qh);
    cudaGetSymbolAddress((void**)&sph, g_sph);
    cudaGetSymbolAddress((void**)&wvh, g_wvh);
    cudaGetSymbolAddress((void**)&woa, g_woa);
    cudaGetSymbolAddress((void**)&wuh, g_wuh);

    static int smem_set = 0;
    if (!smem_set) {
        cudaFuncSetAttribute(gemm_f16<0>, cudaFuncAttributeMaxDynamicSharedMemorySize, SMEM_TOT);
        cudaFuncSetAttribute(gemm_f16<1>, cudaFuncAttributeMaxDynamicSharedMemorySize, SMEM_TOT);
        smem_set = 1;
    }

    // 1) fused weight conversion
    {
        int nb = NB_WV + NB_WU + NB_WO + NB_WA + NB_BIAS;
        convert_weights<<<nb, 256>>>((const float4*)W_v, (const float4*)W_out,
                                     W_off, W_attn, b_off, b_attn,
                                     (uint2*)wvh, (uint2*)wuh, woa, boa_s);
    }
    // 2) value -> fp16
    {
        int n4 = (BSZ * NV * EE) / 4;
        split1_kernel<<<(n4 + 255) / 256, 256>>>((const float4*)value, (uint2*)vh, n4);
    }
    // 3) q = query + query_pos
    {
        int n4 = (BSZ * NQ * EE) / 4;
        split_add1_kernel<<<(n4 + 255) / 256, 256>>>(
            (const float4*)query, (const float4*)qpos, (uint2*)qh, n4);
    }
    // 4) v = value @ W_v + b_v  (M=51200, N=576) -> fp16
    {
        dim3 grid(EE / BN, (BSZ * NV) / BM);
        gemm_f16<1><<<grid, 256, SMEM_TOT>>>(vh, wvh, b_v, vf, BSZ * NV, EE, EE);
    }
    // 5) combined offs|attn = q @ [W_off|W_attn] + bias  (N=864)
    {
        dim3 grid(NOA / BN, (BSZ * NQ) / BM);
        gemm_f16<0><<<grid, 256, SMEM_TOT>>>(qh, woa, boa_s, oa_s, BSZ * NQ, NOA, EE);
    }
    // 6) trilinear sampling + softmax weighting -> fp16
    {
        int warps = BSZ * HEADS * NQ;
        int blocks = (warps + 7) / 8;
        deform_sample<<<blocks, 256>>>(vf, oa_s, sph);
    }
    // 7) out = samp @ W_out + b_out  (N=576)
    {
        dim3 grid(EE / BN, (BSZ * NQ) / BM);
        gemm_f16<0><<<grid, 256, SMEM_TOT>>>(sph, wuh, b_out, out, BSZ * NQ, EE, EE);
    }
}

// round 13
// speedup vs baseline: 2.6095x; 2.6095x over previous
#include <cuda_runtime.h>
#include <cuda_fp16.h>
#include <cstdint>
#include <math.h>

#define BSZ 2
#define HH 64
#define WW 80
#define NQ (HH*WW)          // 5120
#define EE 576
#define HEADS 18
#define HD 32
#define NPTS 12
#define NFR 3
#define DDEP 5
#define NV (NQ*DDEP)        // 25600
#define NOFF (HEADS*NPTS*3) // 648
#define NATT (HEADS*NPTS)   // 216
#define NOA  (NOFF+NATT)    // 864

// ---------------- scratch (device globals; no allocation allowed) ----------
__device__ float g_oa  [(size_t)BSZ*NQ*NOA];
__device__ float g_boa [NOA];

__device__ __align__(128) __half g_vf  [(size_t)BSZ*NV*EE];   // projected v, fp16
__device__ __align__(128) __half g_vh  [(size_t)BSZ*NV*EE];   // value hi
__device__ __align__(128) __half g_qh  [(size_t)BSZ*NQ*EE];   // q hi
__device__ __align__(128) __half g_sph [(size_t)BSZ*NQ*EE];   // samp (fp16)
__device__ __align__(128) __half g_wvh [(size_t)EE*EE];       // W_v hi
__device__ __align__(128) __half g_woa [(size_t)EE*NOA];      // [W_off|W_attn] hi
__device__ __align__(128) __half g_wuh [(size_t)EE*EE];       // W_out hi

// ================= helpers =================================================
__device__ __forceinline__ uint32_t smem_u32(const void* p) {
    uint32_t a;
    asm("{ .reg .u64 t; cvta.to.shared.u64 t, %1; cvt.u32.u64 %0, t; }" : "=r"(a) : "l"(p));
    return a;
}
__device__ __forceinline__ void ldsm_x4(uint32_t* r, uint32_t addr) {
    asm volatile("ldmatrix.sync.aligned.m8n8.x4.shared.b16 {%0,%1,%2,%3}, [%4];"
                 : "=r"(r[0]), "=r"(r[1]), "=r"(r[2]), "=r"(r[3]) : "r"(addr));
}
__device__ __forceinline__ void ldsm_x4_t(uint32_t* r, uint32_t addr) {
    asm volatile("ldmatrix.sync.aligned.m8n8.x4.trans.shared.b16 {%0,%1,%2,%3}, [%4];"
                 : "=r"(r[0]), "=r"(r[1]), "=r"(r[2]), "=r"(r[3]) : "r"(addr));
}
__device__ __forceinline__ void mma_f16(float* c, const uint32_t* a, const uint32_t* b) {
    asm volatile(
        "mma.sync.aligned.m16n8k16.row.col.f32.f16.f16.f32 "
        "{%0,%1,%2,%3}, {%4,%5,%6,%7}, {%8,%9}, {%0,%1,%2,%3};"
        : "+f"(c[0]), "+f"(c[1]), "+f"(c[2]), "+f"(c[3])
        : "r"(a[0]), "r"(a[1]), "r"(a[2]), "r"(a[3]), "r"(b[0]), "r"(b[1]));
}
__device__ __forceinline__ void cp16(uint32_t dst, const void* src) {
    asm volatile("cp.async.ca.shared.global [%0], [%1], 16;" :: "r"(dst), "l"(src));
}
__device__ __forceinline__ void cp16p(uint32_t dst, const void* src, int srcsize) {
    asm volatile("cp.async.ca.shared.global [%0], [%1], 16, %2;" :: "r"(dst), "l"(src), "r"(srcsize));
}
#define CP_COMMIT() asm volatile("cp.async.commit_group;" ::: "memory")
#define CP_WAIT2()  asm volatile("cp.async.wait_group 2;" ::: "memory")

__device__ __forceinline__ uint2 hi4(float4 v) {
    __half2 a = __floats2half2_rn(v.x, v.y);
    __half2 b = __floats2half2_rn(v.z, v.w);
    uint2 r;
    r.x = reinterpret_cast<uint32_t&>(a);
    r.y = reinterpret_cast<uint32_t&>(b);
    return r;
}

// ================= fused weight conversion =================================
#define NB_WV   324
#define NB_WU   324
#define NB_WO   1458
#define NB_WA   486
#define NB_BIAS 4
__global__ void convert_weights(const float4* __restrict__ W_v, const float4* __restrict__ W_out,
                                const float* __restrict__ W_off, const float* __restrict__ W_attn,
                                const float* __restrict__ b_off, const float* __restrict__ b_attn,
                                uint2* __restrict__ wvh, uint2* __restrict__ wuh,
                                __half* __restrict__ woa, float* __restrict__ boa) {
    int blk = blockIdx.x;
    if (blk < NB_WV) {
        int i = blk * 256 + threadIdx.x;
        if (i < (EE * EE) / 4) wvh[i] = hi4(W_v[i]);
    } else if (blk < NB_WV + NB_WU) {
        int i = (blk - NB_WV) * 256 + threadIdx.x;
        if (i < (EE * EE) / 4) wuh[i] = hi4(W_out[i]);
    } else if (blk < NB_WV + NB_WU + NB_WO) {
        int i = (blk - NB_WV - NB_WU) * 256 + threadIdx.x;
        if (i < EE * NOFF) {
            int k = i / NOFF, n = i % NOFF;
            woa[(size_t)k * NOA + n] = __float2half_rn(W_off[i]);
        }
    } else if (blk < NB_WV + NB_WU + NB_WO + NB_WA) {
        int i = (blk - NB_WV - NB_WU - NB_WO) * 256 + threadIdx.x;
        if (i < EE * NATT) {
            int k = i / NATT, n = i % NATT;
            woa[(size_t)k * NOA + NOFF + n] = __float2half_rn(W_attn[i]);
        }
    } else {
        int i = (blk - NB_WV - NB_WU - NB_WO - NB_WA) * 256 + threadIdx.x;
        if (i < NOA) boa[i] = (i < NOFF) ? b_off[i] : b_attn[i - NOFF];
    }
}

__global__ void split1_kernel(const float4* __restrict__ in, uint2* __restrict__ hi, int n4) {
    int i = blockIdx.x * blockDim.x + threadIdx.x;
    if (i < n4) hi[i] = hi4(in[i]);
}
__global__ void split_add1_kernel(const float4* __restrict__ a, const float4* __restrict__ b,
                                  uint2* __restrict__ hi, int n4) {
    int i = blockIdx.x * blockDim.x + threadIdx.x;
    if (i < n4) {
        float4 x = a[i], y = b[i];
        hi[i] = hi4(make_float4(x.x + y.x, x.y + y.y, x.z + y.z, x.w + y.w));
    }
}

// ================= fp16 HMMA GEMM (128x96x32, compact 4-stage) =============
// Block 128x96x32, 8 warps (4m x 2n), warp tile 32x48, <=128 regs -> 2 CTA/SM.
#define BM 128
#define BN 96
#define BK 32
#define STAGES 4
#define SA 80
#define SB 208
#define A_BYTES (128*SA)          // 10240
#define B_BYTES (32*SB)           // 6656
#define OFF_BH A_BYTES
#define STAGE_SZ (A_BYTES + B_BYTES)       // 16896
#define SMEM_TOT (STAGES*STAGE_SZ)         // 67584

template<int OUTF16>
__global__ __launch_bounds__(256, 2)
void gemm_f16(const __half* __restrict__ Ah, const __half* __restrict__ Bh,
              const float* __restrict__ bias, void* __restrict__ Cv,
              int M, int N, int K) {
    extern __shared__ char smem[];
    uint32_t sbase = smem_u32(smem);
    const int tid = threadIdx.x;
    const int lane = tid & 31, wid = tid >> 5;
    const int warp_m = wid & 3, warp_n = wid >> 2;
    const int bm = blockIdx.y * BM;
    const int bn = blockIdx.x * BN;
    const int nchunk = K / BK;

    auto load_chunk = [&](int c, int s) {
        const int k0 = c * BK;
        char* sb = smem + s * STAGE_SZ;
        // A: 128 rows x 64B = 512 x 16B -> 2 per thread
#pragma unroll
        for (int t = 0; t < 2; t++) {
            int idx = tid + t * 256, r = idx >> 2, c4 = idx & 3;
            uint32_t dst = smem_u32(sb + r * SA + c4 * 16);
            cp16(dst, &Ah[(size_t)(bm + r) * K + k0 + c4 * 8]);
        }
        // B: 32 rows x 192B = 384 x 16B
#pragma unroll
        for (int t = 0; t < 2; t++) {
            int idx = tid + t * 256;
            if (idx < 384) {
                int r = idx / 12, g = idx % 12;
                int col = bn + g * 8;
                int sz = (col < N) ? 16 : 0;
                uint32_t dst = smem_u32(sb + OFF_BH + r * SB + g * 16);
                cp16p(dst, &Bh[(size_t)(k0 + r) * N + col], sz);
            }
        }
    };

    float acc[2][6][4];
#pragma unroll
    for (int mi = 0; mi < 2; mi++)
#pragma unroll
        for (int ni = 0; ni < 6; ni++)
#pragma unroll
            for (int j = 0; j < 4; j++) acc[mi][ni][j] = 0.f;

    load_chunk(0, 0); CP_COMMIT();
    load_chunk(1, 1); CP_COMMIT();
    load_chunk(2, 2); CP_COMMIT();

    for (int c = 0; c < nchunk; c++) {
        CP_WAIT2();
        __syncthreads();
        if (c + 3 < nchunk) load_chunk(c + 3, (c + 3) % STAGES);
        CP_COMMIT();

        uint32_t sbuf = sbase + (c % STAGES) * STAGE_SZ;
#pragma unroll
        for (int ks = 0; ks < 2; ks++) {
            uint32_t a_hi[2][4], b_hi[6][2];
#pragma unroll
            for (int mi = 0; mi < 2; mi++) {
                uint32_t ad = sbuf
                    + (warp_m * 32 + mi * 16 + (lane & 15)) * SA
                    + ks * 32 + (lane >> 4) * 16;
                ldsm_x4(a_hi[mi], ad);
            }
#pragma unroll
            for (int nt = 0; nt < 3; nt++) {
                uint32_t bd = sbuf + OFF_BH
                    + (ks * 16 + (lane & 15)) * SB
                    + (warp_n * 48 + nt * 16) * 2 + (lane >> 4) * 16;
                uint32_t r[4];
                ldsm_x4_t(r, bd);
                b_hi[nt * 2][0] = r[0]; b_hi[nt * 2][1] = r[1];
                b_hi[nt * 2 + 1][0] = r[2]; b_hi[nt * 2 + 1][1] = r[3];
            }
#pragma unroll
            for (int mi = 0; mi < 2; mi++)
#pragma unroll
                for (int ni = 0; ni < 6; ni++)
                    mma_f16(acc[mi][ni], a_hi[mi], b_hi[ni]);
        }
    }

    // ---- epilogue (registers -> global; smem untouched) ----
    const int row_base = bm + warp_m * 32 + (lane >> 2);
    const int col_base = bn + warp_n * 48 + (lane & 3) * 2;
#pragma unroll
    for (int mi = 0; mi < 2; mi++)
#pragma unroll
        for (int r2 = 0; r2 < 2; r2++) {
            int row = row_base + mi * 16 + r2 * 8;
#pragma unroll
            for (int ni = 0; ni < 6; ni++) {
                int col = col_base + ni * 8;
                if (col < N) {
                    float ox = acc[mi][ni][r2 * 2 + 0] + bias[col];
                    float oy = acc[mi][ni][r2 * 2 + 1] + bias[col + 1];
                    if (OUTF16) {
                        __half2 pk = __floats2half2_rn(ox, oy);
                        *reinterpret_cast<__half2*>(
                            &((__half*)Cv)[(size_t)row * N + col]) = pk;
                    } else {
                        float2 o; o.x = ox; o.y = oy;
                        *reinterpret_cast<float2*>(&((float*)Cv)[(size_t)row * N + col]) = o;
                    }
                }
            }
        }
}

// ================= deformable 3D trilinear sampling (fp16 v) ===============
// Branchy (warp-uniform) corner skipping + early whole-point z-skip +
// algebraically simplified coordinates + fast exp.
__global__ __launch_bounds__(256)
void deform_sample(const __half* __restrict__ v, const float* __restrict__ oa,
                   __half* __restrict__ oh) {
    int wg = (blockIdx.x * blockDim.x + threadIdx.x) >> 5;
    int lane = threadIdx.x & 31;
    const int total = BSZ * HEADS * NQ;
    if (wg >= total) return;

    int q    = wg % NQ;
    int head = (wg / NQ) % HEADS;
    int b    = wg / (NQ * HEADS);
    size_t row = (size_t)b * NQ + q;

    int qx = q % WW;
    int qy = q / WW;

    const float* lgp = oa + row * NOA + NOFF + head * NPTS;
    float wt[NPTS];
    float mx = -1e30f;
#pragma unroll
    for (int p = 0; p < NPTS; p++) mx = fmaxf(mx, lgp[p]);
    float s = 0.f;
#pragma unroll
    for (int p = 0; p < NPTS; p++) { wt[p] = __expf(lgp[p] - mx); s += wt[p]; }
    float invs = 1.f / s;

    const float* offp = oa + row * NOA + head * NPTS * 3;
    const __half* vbh = v + (size_t)b * NV * EE + head * HD + lane;

    float acc = 0.f;
#pragma unroll
    for (int p = 0; p < NPTS; p++) {
        float oz = offp[p * 3 + 2];
        // z = (oz/NFR)*DDEP - 0.5 ; empty z-range -> whole point contributes 0
        float z = oz * ((float)DDEP / (float)NFR) - 0.5f;
        if (z <= -1.f || z >= (float)DDEP) continue;

        float ox = offp[p * 3 + 0];
        float oy = offp[p * 3 + 1];
        // (refx + ox/W)*W - 0.5 == qx + ox  (refx*W = qx+0.5)
        float x = (float)qx + ox;
        float y = (float)qy + oy;
        float x0f = floorf(x), y0f = floorf(y), z0f = floorf(z);
        float fx = x - x0f, fy = y - y0f, fz = z - z0f;
        int ix0 = (int)x0f, iy0 = (int)y0f, iz0 = (int)z0f;
        float ap = wt[p] * invs;
#pragma unroll
        for (int dz = 0; dz < 2; dz++) {
            int zi = iz0 + dz;
            if ((unsigned)zi >= DDEP) continue;
            float wz = dz ? fz : (1.f - fz);
#pragma unroll
            for (int dy = 0; dy < 2; dy++) {
                int yi = iy0 + dy;
                if ((unsigned)yi >= HH) continue;
                float wzy = wz * (dy ? fy : (1.f - fy));
#pragma unroll
                for (int dx = 0; dx < 2; dx++) {
                    int xi = ix0 + dx;
                    if ((unsigned)xi >= WW) continue;
                    float wgt = wzy * (dx ? fx : (1.f - fx));
                    int idx = (zi * HH + yi) * WW + xi;
                    acc += ap * wgt * __half2float(__ldg(&vbh[(size_t)idx * EE]));
                }
            }
        }
    }
    oh[row * EE + head * HD + lane] = __float2half_rn(acc);
}

// ================= launch ==================================================
extern "C" void kernel_launch(void* const* d_in, const int* in_sizes, int n_in,
                              void* d_out, int out_size) {
    const float* query  = (const float*)d_in[0];
    const float* value  = (const float*)d_in[1];
    const float* qpos   = (const float*)d_in[2];
    const float* W_off  = (const float*)d_in[3];
    const float* b_off  = (const float*)d_in[4];
    const float* W_attn = (const float*)d_in[5];
    const float* b_attn = (const float*)d_in[6];
    const float* W_v    = (const float*)d_in[7];
    const float* b_v    = (const float*)d_in[8];
    const float* W_out  = (const float*)d_in[9];
    const float* b_out  = (const float*)d_in[10];
    float* out = (float*)d_out;

    float *oa_s, *boa_s;
    __half *vf, *vh, *qh, *sph, *wvh, *woa, *wuh;
    cudaGetSymbolAddress((void**)&oa_s,  g_oa);
    cudaGetSymbolAddress((void**)&boa_s, g_boa);
    cudaGetSymbolAddress((void**)&vf,  g_vf);
    cudaGetSymbolAddress((void**)&vh,  g_vh);
    cudaGetSymbolAddress((void**)&qh,  g_qh);
    cudaGetSymbolAddress((void**)&sph, g_sph);
    cudaGetSymbolAddress((void**)&wvh, g_wvh);
    cudaGetSymbolAddress((void**)&woa, g_woa);
    cudaGetSymbolAddress((void**)&wuh, g_wuh);

    static int smem_set = 0;
    if (!smem_set) {
        cudaFuncSetAttribute(gemm_f16<0>, cudaFuncAttributeMaxDynamicSharedMemorySize, SMEM_TOT);
        cudaFuncSetAttribute(gemm_f16<1>, cudaFuncAttributeMaxDynamicSharedMemorySize, SMEM_TOT);
        smem_set = 1;
    }

    // 1) fused weight conversion
    {
        int nb = NB_WV + NB_WU + NB_WO + NB_WA + NB_BIAS;
        convert_weights<<<nb, 256>>>((const float4*)W_v, (const float4*)W_out,
                                     W_off, W_attn, b_off, b_attn,
                                     (uint2*)wvh, (uint2*)wuh, woa, boa_s);
    }
    // 2) value -> fp16
    {
        int n4 = (BSZ * NV * EE) / 4;
        split1_kernel<<<(n4 + 255) / 256, 256>>>((const float4*)value, (uint2*)vh, n4);
    }
    // 3) q = query + query_pos
    {
        int n4 = (BSZ * NQ * EE) / 4;
        split_add1_kernel<<<(n4 + 255) / 256, 256>>>(
            (const float4*)query, (const float4*)qpos, (uint2*)qh, n4);
    }
    // 4) v = value @ W_v + b_v  (M=51200, N=576) -> fp16
    {
        dim3 grid(EE / BN, (BSZ * NV) / BM);
        gemm_f16<1><<<grid, 256, SMEM_TOT>>>(vh, wvh, b_v, vf, BSZ * NV, EE, EE);
    }
    // 5) combined offs|attn = q @ [W_off|W_attn] + bias  (N=864)
    {
        dim3 grid(NOA / BN, (BSZ * NQ) / BM);
        gemm_f16<0><<<grid, 256, SMEM_TOT>>>(qh, woa, boa_s, oa_s, BSZ * NQ, NOA, EE);
    }
    // 6) trilinear sampling + softmax weighting -> fp16
    {
        int warps = BSZ * HEADS * NQ;
        int blocks = (warps + 7) / 8;
        deform_sample<<<blocks, 256>>>(vf, oa_s, sph);
    }
    // 7) out = samp @ W_out + b_out  (N=576)
    {
        dim3 grid(EE / BN, (BSZ * NQ) / BM);
        gemm_f16<0><<<grid, 256, SMEM_TOT>>>(sph, wuh, b_out, out, BSZ * NQ, EE, EE);
    }
}

// round 14
// speedup vs baseline: 2.6322x; 1.0087x over previous
#include <cuda_runtime.h>
#include <cuda_fp16.h>
#include <cstdint>
#include <math.h>

#define BSZ 2
#define HH 64
#define WW 80
#define NQ (HH*WW)          // 5120
#define EE 576
#define HEADS 18
#define HD 32
#define NPTS 12
#define NFR 3
#define DDEP 5
#define NV (NQ*DDEP)        // 25600
#define NOFF (HEADS*NPTS*3) // 648
#define NATT (HEADS*NPTS)   // 216
#define NOA  (NOFF+NATT)    // 864

// ---------------- scratch (device globals; no allocation allowed) ----------
__device__ float g_oa  [(size_t)BSZ*NQ*NOA];
__device__ float g_boa [NOA];

__device__ __align__(128) __half g_vf  [(size_t)BSZ*NV*EE];   // projected v, fp16
__device__ __align__(128) __half g_vh  [(size_t)BSZ*NV*EE];   // value hi
__device__ __align__(128) __half g_qh  [(size_t)BSZ*NQ*EE];   // q hi
__device__ __align__(128) __half g_sph [(size_t)BSZ*NQ*EE];   // samp (fp16)
__device__ __align__(128) __half g_wvh [(size_t)EE*EE];       // W_v hi
__device__ __align__(128) __half g_woa [(size_t)EE*NOA];      // [W_off|W_attn] hi
__device__ __align__(128) __half g_wuh [(size_t)EE*EE];       // W_out hi

// ================= helpers =================================================
__device__ __forceinline__ uint32_t smem_u32(const void* p) {
    uint32_t a;
    asm("{ .reg .u64 t; cvta.to.shared.u64 t, %1; cvt.u32.u64 %0, t; }" : "=r"(a) : "l"(p));
    return a;
}
__device__ __forceinline__ void ldsm_x4(uint32_t* r, uint32_t addr) {
    asm volatile("ldmatrix.sync.aligned.m8n8.x4.shared.b16 {%0,%1,%2,%3}, [%4];"
                 : "=r"(r[0]), "=r"(r[1]), "=r"(r[2]), "=r"(r[3]) : "r"(addr));
}
__device__ __forceinline__ void ldsm_x4_t(uint32_t* r, uint32_t addr) {
    asm volatile("ldmatrix.sync.aligned.m8n8.x4.trans.shared.b16 {%0,%1,%2,%3}, [%4];"
                 : "=r"(r[0]), "=r"(r[1]), "=r"(r[2]), "=r"(r[3]) : "r"(addr));
}
__device__ __forceinline__ void mma_f16(float* c, const uint32_t* a, const uint32_t* b) {
    asm volatile(
        "mma.sync.aligned.m16n8k16.row.col.f32.f16.f16.f32 "
        "{%0,%1,%2,%3}, {%4,%5,%6,%7}, {%8,%9}, {%0,%1,%2,%3};"
        : "+f"(c[0]), "+f"(c[1]), "+f"(c[2]), "+f"(c[3])
        : "r"(a[0]), "r"(a[1]), "r"(a[2]), "r"(a[3]), "r"(b[0]), "r"(b[1]));
}
__device__ __forceinline__ void cp16(uint32_t dst, const void* src) {
    asm volatile("cp.async.ca.shared.global [%0], [%1], 16;" :: "r"(dst), "l"(src));
}
__device__ __forceinline__ void cp16p(uint32_t dst, const void* src, int srcsize) {
    asm volatile("cp.async.ca.shared.global [%0], [%1], 16, %2;" :: "r"(dst), "l"(src), "r"(srcsize));
}
#define CP_COMMIT() asm volatile("cp.async.commit_group;" ::: "memory")
#define CP_WAIT2()  asm volatile("cp.async.wait_group 2;" ::: "memory")

__device__ __forceinline__ uint2 hi4(float4 v) {
    __half2 a = __floats2half2_rn(v.x, v.y);
    __half2 b = __floats2half2_rn(v.z, v.w);
    uint2 r;
    r.x = reinterpret_cast<uint32_t&>(a);
    r.y = reinterpret_cast<uint32_t&>(b);
    return r;
}

// ================= fused weight conversion =================================
#define NB_WV   324
#define NB_WU   324
#define NB_WO   1458
#define NB_WA   486
#define NB_BIAS 4
__global__ void convert_weights(const float4* __restrict__ W_v, const float4* __restrict__ W_out,
                                const float* __restrict__ W_off, const float* __restrict__ W_attn,
                                const float* __restrict__ b_off, const float* __restrict__ b_attn,
                                uint2* __restrict__ wvh, uint2* __restrict__ wuh,
                                __half* __restrict__ woa, float* __restrict__ boa) {
    int blk = blockIdx.x;
    if (blk < NB_WV) {
        int i = blk * 256 + threadIdx.x;
        if (i < (EE * EE) / 4) wvh[i] = hi4(W_v[i]);
    } else if (blk < NB_WV + NB_WU) {
        int i = (blk - NB_WV) * 256 + threadIdx.x;
        if (i < (EE * EE) / 4) wuh[i] = hi4(W_out[i]);
    } else if (blk < NB_WV + NB_WU + NB_WO) {
        int i = (blk - NB_WV - NB_WU) * 256 + threadIdx.x;
        if (i < EE * NOFF) {
            int k = i / NOFF, n = i % NOFF;
            woa[(size_t)k * NOA + n] = __float2half_rn(W_off[i]);
        }
    } else if (blk < NB_WV + NB_WU + NB_WO + NB_WA) {
        int i = (blk - NB_WV - NB_WU - NB_WO) * 256 + threadIdx.x;
        if (i < EE * NATT) {
            int k = i / NATT, n = i % NATT;
            woa[(size_t)k * NOA + NOFF + n] = __float2half_rn(W_attn[i]);
        }
    } else {
        int i = (blk - NB_WV - NB_WU - NB_WO - NB_WA) * 256 + threadIdx.x;
        if (i < NOA) boa[i] = (i < NOFF) ? b_off[i] : b_attn[i - NOFF];
    }
}

// ================= fused activation conversion =============================
// value -> fp16  AND  (query + query_pos) -> fp16, one launch.
#define NB_VAL ((BSZ*NV*EE/4 + 255)/256)   // 14400
#define NB_Q   ((BSZ*NQ*EE/4 + 255)/256)   // 5760
__global__ void convert_acts(const float4* __restrict__ value, const float4* __restrict__ query,
                             const float4* __restrict__ qpos,
                             uint2* __restrict__ vh, uint2* __restrict__ qh) {
    int blk = blockIdx.x;
    if (blk < NB_VAL) {
        int i = blk * 256 + threadIdx.x;
        if (i < BSZ * NV * EE / 4) vh[i] = hi4(value[i]);
    } else {
        int i = (blk - NB_VAL) * 256 + threadIdx.x;
        if (i < BSZ * NQ * EE / 4) {
            float4 x = query[i], y = qpos[i];
            qh[i] = hi4(make_float4(x.x + y.x, x.y + y.y, x.z + y.z, x.w + y.w));
        }
    }
}

// ================= fp16 HMMA GEMM (128x96x32, compact 4-stage) =============
#define BM 128
#define BN 96
#define BK 32
#define STAGES 4
#define SA 80
#define SB 208
#define A_BYTES (128*SA)          // 10240
#define B_BYTES (32*SB)           // 6656
#define OFF_BH A_BYTES
#define STAGE_SZ (A_BYTES + B_BYTES)       // 16896
#define SMEM_TOT (STAGES*STAGE_SZ)         // 67584

template<int OUTF16>
__global__ __launch_bounds__(256, 2)
void gemm_f16(const __half* __restrict__ Ah, const __half* __restrict__ Bh,
              const float* __restrict__ bias, void* __restrict__ Cv,
              int M, int N, int K) {
    extern __shared__ char smem[];
    uint32_t sbase = smem_u32(smem);
    const int tid = threadIdx.x;
    const int lane = tid & 31, wid = tid >> 5;
    const int warp_m = wid & 3, warp_n = wid >> 2;
    const int bm = blockIdx.y * BM;
    const int bn = blockIdx.x * BN;
    const int nchunk = K / BK;

    auto load_chunk = [&](int c, int s) {
        const int k0 = c * BK;
        char* sb = smem + s * STAGE_SZ;
#pragma unroll
        for (int t = 0; t < 2; t++) {
            int idx = tid + t * 256, r = idx >> 2, c4 = idx & 3;
            uint32_t dst = smem_u32(sb + r * SA + c4 * 16);
            cp16(dst, &Ah[(size_t)(bm + r) * K + k0 + c4 * 8]);
        }
#pragma unroll
        for (int t = 0; t < 2; t++) {
            int idx = tid + t * 256;
            if (idx < 384) {
                int r = idx / 12, g = idx % 12;
                int col = bn + g * 8;
                int sz = (col < N) ? 16 : 0;
                uint32_t dst = smem_u32(sb + OFF_BH + r * SB + g * 16);
                cp16p(dst, &Bh[(size_t)(k0 + r) * N + col], sz);
            }
        }
    };

    float acc[2][6][4];
#pragma unroll
    for (int mi = 0; mi < 2; mi++)
#pragma unroll
        for (int ni = 0; ni < 6; ni++)
#pragma unroll
            for (int j = 0; j < 4; j++) acc[mi][ni][j] = 0.f;

    load_chunk(0, 0); CP_COMMIT();
    load_chunk(1, 1); CP_COMMIT();
    load_chunk(2, 2); CP_COMMIT();

    for (int c = 0; c < nchunk; c++) {
        CP_WAIT2();
        __syncthreads();
        if (c + 3 < nchunk) load_chunk(c + 3, (c + 3) % STAGES);
        CP_COMMIT();

        uint32_t sbuf = sbase + (c % STAGES) * STAGE_SZ;
#pragma unroll
        for (int ks = 0; ks < 2; ks++) {
            uint32_t a_hi[2][4], b_hi[6][2];
#pragma unroll
            for (int mi = 0; mi < 2; mi++) {
                uint32_t ad = sbuf
                    + (warp_m * 32 + mi * 16 + (lane & 15)) * SA
                    + ks * 32 + (lane >> 4) * 16;
                ldsm_x4(a_hi[mi], ad);
            }
#pragma unroll
            for (int nt = 0; nt < 3; nt++) {
                uint32_t bd = sbuf + OFF_BH
                    + (ks * 16 + (lane & 15)) * SB
                    + (warp_n * 48 + nt * 16) * 2 + (lane >> 4) * 16;
                uint32_t r[4];
                ldsm_x4_t(r, bd);
                b_hi[nt * 2][0] = r[0]; b_hi[nt * 2][1] = r[1];
                b_hi[nt * 2 + 1][0] = r[2]; b_hi[nt * 2 + 1][1] = r[3];
            }
#pragma unroll
            for (int mi = 0; mi < 2; mi++)
#pragma unroll
                for (int ni = 0; ni < 6; ni++)
                    mma_f16(acc[mi][ni], a_hi[mi], b_hi[ni]);
        }
    }

    // ---- epilogue ----
    const int row_base = bm + warp_m * 32 + (lane >> 2);
    const int col_base = bn + warp_n * 48 + (lane & 3) * 2;
#pragma unroll
    for (int mi = 0; mi < 2; mi++)
#pragma unroll
        for (int r2 = 0; r2 < 2; r2++) {
            int row = row_base + mi * 16 + r2 * 8;
#pragma unroll
            for (int ni = 0; ni < 6; ni++) {
                int col = col_base + ni * 8;
                if (col < N) {
                    float ox = acc[mi][ni][r2 * 2 + 0] + bias[col];
                    float oy = acc[mi][ni][r2 * 2 + 1] + bias[col + 1];
                    if (OUTF16) {
                        __half2 pk = __floats2half2_rn(ox, oy);
                        *reinterpret_cast<__half2*>(
                            &((__half*)Cv)[(size_t)row * N + col]) = pk;
                    } else {
                        float2 o; o.x = ox; o.y = oy;
                        *reinterpret_cast<float2*>(&((float*)Cv)[(size_t)row * N + col]) = o;
                    }
                }
            }
        }
}

// ================= deformable 3D trilinear sampling (fp16 v) ===============
// z-skip + fast path (all 8 corners in-bounds -> unconditional batched loads)
// + guarded fallback at borders.
__global__ __launch_bounds__(256)
void deform_sample(const __half* __restrict__ v, const float* __restrict__ oa,
                   __half* __restrict__ oh) {
    int wg = (blockIdx.x * blockDim.x + threadIdx.x) >> 5;
    int lane = threadIdx.x & 31;
    const int total = BSZ * HEADS * NQ;
    if (wg >= total) return;

    int q    = wg % NQ;
    int head = (wg / NQ) % HEADS;
    int b    = wg / (NQ * HEADS);
    size_t row = (size_t)b * NQ + q;

    int qx = q % WW;
    int qy = q / WW;

    const float* lgp = oa + row * NOA + NOFF + head * NPTS;
    float wt[NPTS];
    float mx = -1e30f;
#pragma unroll
    for (int p = 0; p < NPTS; p++) mx = fmaxf(mx, lgp[p]);
    float s = 0.f;
#pragma unroll
    for (int p = 0; p < NPTS; p++) { wt[p] = __expf(lgp[p] - mx); s += wt[p]; }
    float invs = 1.f / s;

    const float* offp = oa + row * NOA + head * NPTS * 3;
    const __half* vbh = v + (size_t)b * NV * EE + head * HD + lane;

    float acc = 0.f;
#pragma unroll
    for (int p = 0; p < NPTS; p++) {
        float oz = offp[p * 3 + 2];
        float z = oz * ((float)DDEP / (float)NFR) - 0.5f;
        if (z <= -1.f || z >= (float)DDEP) continue;

        float ox = offp[p * 3 + 0];
        float oy = offp[p * 3 + 1];
        float x = (float)qx + ox;       // == (refx + ox/W)*W - 0.5
        float y = (float)qy + oy;
        float x0f = floorf(x), y0f = floorf(y), z0f = floorf(z);
        float fx = x - x0f, fy = y - y0f, fz = z - z0f;
        int ix0 = (int)x0f, iy0 = (int)y0f, iz0 = (int)z0f;
        float ap = wt[p] * invs;

        bool fast = (ix0 >= 0) & (ix0 < WW - 1) & (iy0 >= 0) & (iy0 < HH - 1)
                  & (iz0 >= 0) & (iz0 < DDEP - 1);
        if (fast) {
            // all 8 corners valid: unconditional, batched loads
            size_t base = ((size_t)(iz0 * HH + iy0) * WW + ix0) * EE;
            const __half* c0 = vbh + base;
            float v000 = __half2float(__ldg(c0));
            float v001 = __half2float(__ldg(c0 + EE));
            float v010 = __half2float(__ldg(c0 + (size_t)WW * EE));
            float v011 = __half2float(__ldg(c0 + (size_t)(WW + 1) * EE));
            float v100 = __half2float(__ldg(c0 + (size_t)(HH * WW) * EE));
            float v101 = __half2float(__ldg(c0 + (size_t)(HH * WW + 1) * EE));
            float v110 = __half2float(__ldg(c0 + (size_t)(HH * WW + WW) * EE));
            float v111 = __half2float(__ldg(c0 + (size_t)(HH * WW + WW + 1) * EE));
            float gx0 = 1.f - fx, gy0 = 1.f - fy, gz0 = 1.f - fz;
            float s00 = v000 * gx0 + v001 * fx;
            float s01 = v010 * gx0 + v011 * fx;
            float s10 = v100 * gx0 + v101 * fx;
            float s11 = v110 * gx0 + v111 * fx;
            float t0 = s00 * gy0 + s01 * fy;
            float t1 = s10 * gy0 + s11 * fy;
            acc += ap * (t0 * gz0 + t1 * fz);
        } else {
#pragma unroll
            for (int dz = 0; dz < 2; dz++) {
                int zi = iz0 + dz;
                if ((unsigned)zi >= DDEP) continue;
                float wz = dz ? fz : (1.f - fz);
#pragma unroll
                for (int dy = 0; dy < 2; dy++) {
                    int yi = iy0 + dy;
                    if ((unsigned)yi >= HH) continue;
                    float wzy = wz * (dy ? fy : (1.f - fy));
#pragma unroll
                    for (int dx = 0; dx < 2; dx++) {
                        int xi = ix0 + dx;
                        if ((unsigned)xi >= WW) continue;
                        float wgt = wzy * (dx ? fx : (1.f - fx));
                        int idx = (zi * HH + yi) * WW + xi;
                        acc += ap * wgt * __half2float(__ldg(&vbh[(size_t)idx * EE]));
                    }
                }
            }
        }
    }
    oh[row * EE + head * HD + lane] = __float2half_rn(acc);
}

// ================= launch ==================================================
extern "C" void kernel_launch(void* const* d_in, const int* in_sizes, int n_in,
                              void* d_out, int out_size) {
    const float* query  = (const float*)d_in[0];
    const float* value  = (const float*)d_in[1];
    const float* qpos   = (const float*)d_in[2];
    const float* W_off  = (const float*)d_in[3];
    const float* b_off  = (const float*)d_in[4];
    const float* W_attn = (const float*)d_in[5];
    const float* b_attn = (const float*)d_in[6];
    const float* W_v    = (const float*)d_in[7];
    const float* b_v    = (const float*)d_in[8];
    const float* W_out  = (const float*)d_in[9];
    const float* b_out  = (const float*)d_in[10];
    float* out = (float*)d_out;

    float *oa_s, *boa_s;
    __half *vf, *vh, *qh, *sph, *wvh, *woa, *wuh;
    cudaGetSymbolAddress((void**)&oa_s,  g_oa);
    cudaGetSymbolAddress((void**)&boa_s, g_boa);
    cudaGetSymbolAddress((void**)&vf,  g_vf);
    cudaGetSymbolAddress((void**)&vh,  g_vh);
    cudaGetSymbolAddress((void**)&qh,  g_qh);
    cudaGetSymbolAddress((void**)&sph, g_sph);
    cudaGetSymbolAddress((void**)&wvh, g_wvh);
    cudaGetSymbolAddress((void**)&woa, g_woa);
    cudaGetSymbolAddress((void**)&wuh, g_wuh);

    static int smem_set = 0;
    if (!smem_set) {
        cudaFuncSetAttribute(gemm_f16<0>, cudaFuncAttributeMaxDynamicSharedMemorySize, SMEM_TOT);
        cudaFuncSetAttribute(gemm_f16<1>, cudaFuncAttributeMaxDynamicSharedMemorySize, SMEM_TOT);
        smem_set = 1;
    }

    // 1) fused weight conversion
    {
        int nb = NB_WV + NB_WU + NB_WO + NB_WA + NB_BIAS;
        convert_weights<<<nb, 256>>>((const float4*)W_v, (const float4*)W_out,
                                     W_off, W_attn, b_off, b_attn,
                                     (uint2*)wvh, (uint2*)wuh, woa, boa_s);
    }
    // 2) fused activation conversion (value + q)
    {
        convert_acts<<<NB_VAL + NB_Q, 256>>>((const float4*)value, (const float4*)query,
                                             (const float4*)qpos, (uint2*)vh, (uint2*)qh);
    }
    // 3) v = value @ W_v + b_v  (M=51200, N=576) -> fp16
    {
        dim3 grid(EE / BN, (BSZ * NV) / BM);
        gemm_f16<1><<<grid, 256, SMEM_TOT>>>(vh, wvh, b_v, vf, BSZ * NV, EE, EE);
    }
    // 4) combined offs|attn = q @ [W_off|W_attn] + bias  (N=864)
    {
        dim3 grid(NOA / BN, (BSZ * NQ) / BM);
        gemm_f16<0><<<grid, 256, SMEM_TOT>>>(qh, woa, boa_s, oa_s, BSZ * NQ, NOA, EE);
    }
    // 5) trilinear sampling + softmax weighting -> fp16
    {
        int warps = BSZ * HEADS * NQ;
        int blocks = (warps + 7) / 8;
        deform_sample<<<blocks, 256>>>(vf, oa_s, sph);
    }
    // 6) out = samp @ W_out + b_out  (N=576)
    {
        dim3 grid(EE / BN, (BSZ * NQ) / BM);
        gemm_f16<0><<<grid, 256, SMEM_TOT>>>(sph, wuh, b_out, out, BSZ * NQ, EE, EE);
    }
}